// round 10
// baseline (speedup 1.0000x reference)
#include <cuda_runtime.h>

// TimeSeriesWineSNN: 3-layer LIF SNN, T=1000, B=4096, dims 8 -> 28 -> 8 -> 4.
// Mapping: 8 threads per batch element (4 batch groups per warp).
// Arithmetic config E (R8 + warp-shuffle-butterfly dot association):
//  - dot products individually ROUNDED (__fmul_rn), bias __fadd_rn LAST
//  - dot reduction = XLA:GPU shfl-down butterfly:
//      K=8  (layers 1,3): offsets 4,2,1 (segment width 8)
//      K=28 (layer 2):    lanes 28..31 = 0, offsets 16,8,4,2,1 (width 32)
//  - membrane: CONTRACTED  mn = fma(0.9, m, cur), exact -1.0 subtract on reset
//  - comparators on exact fp32 values, reset from previous membrane
// (Resubmission — R9 bench was an infra failure, no kernel signal.)

constexpr int T_STEPS = 1000;
constexpr int BATCH   = 4096;
constexpr int NIN     = 8;
constexpr int NH1     = 28;
constexpr int NH2     = 8;
constexpr int NOUT    = 4;

// lane-0 value of a shfl-down butterfly over 8 lanes (offsets 4,2,1)
__device__ __forceinline__ float butterfly8(const float* __restrict__ p) {
    float v0 = __fadd_rn(p[0], p[4]);
    float v1 = __fadd_rn(p[1], p[5]);
    float v2 = __fadd_rn(p[2], p[6]);
    float v3 = __fadd_rn(p[3], p[7]);
    v0 = __fadd_rn(v0, v2);
    v1 = __fadd_rn(v1, v3);
    return __fadd_rn(v0, v1);
}

__global__ void __launch_bounds__(128)
snn_kernel(const float* __restrict__ x,
           const float* __restrict__ W1, const float* __restrict__ b1,
           const float* __restrict__ W2, const float* __restrict__ b2,
           const float* __restrict__ W3, const float* __restrict__ b3,
           float* __restrict__ out)
{
    const int tid = blockIdx.x * 128 + threadIdx.x;
    const int j   = tid & 7;          // lane within 8-thread group
    const int b   = tid >> 3;         // batch element
    const int lg  = threadIdx.x >> 3; // local group index 0..15

    __shared__ __align__(16) float s1buf[2][16][32];

    // ---- weights into registers (fake neurons for n >= 28 get zero weights) ----
    float w1[4][8], bias1[4];
#pragma unroll
    for (int r = 0; r < 4; ++r) {
        const int n = 4 * j + r;
        const bool v = (n < NH1);
        bias1[r] = v ? __ldg(&b1[n]) : 0.0f;
#pragma unroll
        for (int i = 0; i < 8; ++i)
            w1[r][i] = v ? __ldg(&W1[n * NIN + i]) : 0.0f;
    }
    float w2[NH1];
#pragma unroll
    for (int k = 0; k < NH1; ++k) w2[k] = __ldg(&W2[j * NH1 + k]);
    const float bias2 = __ldg(&b2[j]);

    const bool j4 = (j < 4);
    float w3[8];
#pragma unroll
    for (int i = 0; i < 8; ++i) w3[i] = j4 ? __ldg(&W3[j * NH2 + i]) : 0.0f;
    const float bias3 = j4 ? __ldg(&b3[j]) : 0.0f;

    // ---- state ----
    float m1[4] = {0.f, 0.f, 0.f, 0.f};
    float m2 = 0.f, m3 = 0.f;

    // ---- output regions: mem3 | spk3 | spk1 | spk2 ----
    float* __restrict__ mem3_o = out;
    float* __restrict__ spk3_o = mem3_o + (size_t)T_STEPS * BATCH * NOUT;
    float* __restrict__ spk1_o = spk3_o + (size_t)T_STEPS * BATCH * NOUT;
    float* __restrict__ spk2_o = spk1_o + (size_t)T_STEPS * BATCH * NH1;

    const float* __restrict__ xp = x + (size_t)b * NIN + j;
    const size_t xstride = (size_t)BATCH * NIN;   // elements per timestep

    // prefetch ring (depth 4)
    float pf0 = xp[0];
    float pf1 = xp[xstride];
    float pf2 = xp[2 * xstride];
    float pf3 = xp[3 * xstride];

    // LIF update: reset from previous m; CONTRACTED leak+integrate;
    // exact -1.0 subtract; spike on new m.
    auto lif = [](float& m, float cur, float& spk) {
        const float mo = m;
        float mn = __fmaf_rn(0.9f, mo, cur);
        if (__fsub_rn(mo, 1.0f) > 0.0f) mn = __fsub_rn(mn, 1.0f);
        m = mn;
        spk = (__fsub_rn(mn, 1.0f) > 0.0f) ? 1.0f : 0.0f;
    };

    auto step = [&](int t, float xv, int bufi) {
        // broadcast x within the 8-lane group
        float xs[8];
#pragma unroll
        for (int i = 0; i < 8; ++i)
            xs[i] = __shfl_sync(0xffffffffu, xv, i, 8);

        // layer 1: 4 neurons per lane; rounded products, butterfly-8 sum, bias last
        float c[4];
#pragma unroll
        for (int r = 0; r < 4; ++r) {
            float p[8];
#pragma unroll
            for (int i = 0; i < 8; ++i)
                p[i] = __fmul_rn(w1[r][i], xs[i]);
            c[r] = __fadd_rn(butterfly8(p), bias1[r]);
        }

        float4 sp;
        lif(m1[0], c[0], sp.x);
        lif(m1[1], c[1], sp.y);
        lif(m1[2], c[2], sp.z);
        lif(m1[3], c[3], sp.w);

        // s1 exchange (lane 7 writes pad cols 28..31, never read)
        *reinterpret_cast<float4*>(&s1buf[bufi][lg][4 * j]) = sp;
        if (j < 7)
            *reinterpret_cast<float4*>(spk1_o + ((size_t)t * BATCH + b) * NH1 + 4 * j) = sp;
        __syncwarp();

        // layer 2: neuron j; rounded products, 32-lane butterfly (lanes 28..31 = 0),
        // bias last
        float s1v[NH1];
#pragma unroll
        for (int q = 0; q < 7; ++q) {
            float4 s = *reinterpret_cast<const float4*>(&s1buf[bufi][lg][4 * q]);
            s1v[4 * q + 0] = s.x; s1v[4 * q + 1] = s.y;
            s1v[4 * q + 2] = s.z; s1v[4 * q + 3] = s.w;
        }
        float v[32];
#pragma unroll
        for (int k = 0; k < NH1; ++k) v[k] = __fmul_rn(w2[k], s1v[k]);
#pragma unroll
        for (int k = NH1; k < 32; ++k) v[k] = 0.0f;
        // shfl-down butterfly, lane-0 dependency cone only
#pragma unroll
        for (int i = 0; i < 16; ++i) v[i] = __fadd_rn(v[i], v[i + 16]);
#pragma unroll
        for (int i = 0; i < 8;  ++i) v[i] = __fadd_rn(v[i], v[i + 8]);
#pragma unroll
        for (int i = 0; i < 4;  ++i) v[i] = __fadd_rn(v[i], v[i + 4]);
        v[0] = __fadd_rn(v[0], v[2]);
        v[1] = __fadd_rn(v[1], v[3]);
        float a2 = __fadd_rn(__fadd_rn(v[0], v[1]), bias2);

        float s2;
        lif(m2, a2, s2);
        spk2_o[((size_t)t * BATCH + b) * NH2 + j] = s2;

        // layer 3: rounded products over shuffled s2, butterfly-8 sum, bias last
        float p3[8];
#pragma unroll
        for (int i = 0; i < 8; ++i)
            p3[i] = __fmul_rn(w3[i], __shfl_sync(0xffffffffu, s2, i, 8));
        float a3 = __fadd_rn(butterfly8(p3), bias3);

        float s3;
        lif(m3, a3, s3);
        if (j4) {
            mem3_o[((size_t)t * BATCH + b) * NOUT + j] = m3;
            spk3_o[((size_t)t * BATCH + b) * NOUT + j] = s3;
        }
    };

    for (int t = 0; t < T_STEPS; t += 4) {
        const float x0 = pf0, x1 = pf1, x2 = pf2, x3 = pf3;
        if (t + 4 < T_STEPS) {
            const float* p = xp + (size_t)(t + 4) * xstride;
            pf0 = p[0];
            pf1 = p[xstride];
            pf2 = p[2 * xstride];
            pf3 = p[3 * xstride];
        }
        step(t + 0, x0, 0);
        step(t + 1, x1, 1);
        step(t + 2, x2, 0);
        step(t + 3, x3, 1);
    }
}

extern "C" void kernel_launch(void* const* d_in, const int* in_sizes, int n_in,
                              void* d_out, int out_size) {
    const float* x  = (const float*)d_in[0];
    const float* W1 = (const float*)d_in[1];
    const float* b1 = (const float*)d_in[2];
    const float* W2 = (const float*)d_in[3];
    const float* b2 = (const float*)d_in[4];
    const float* W3 = (const float*)d_in[5];
    const float* b3 = (const float*)d_in[6];

    const int threads = 128;
    const int blocks  = (BATCH * 8) / threads;  // 256
    snn_kernel<<<blocks, threads>>>(x, W1, b1, W2, b2, W3, b3, (float*)d_out);
}